// round 15
// baseline (speedup 1.0000x reference)
#include <cuda_runtime.h>
#include <cuda_fp16.h>
#include <cfloat>
#include <cstdint>

#define HEADS 16
#define DH 64
#define SCALE 0.125f
#define WSCALE 16384.0f

// scratch (__device__ globals; no cudaMalloc allowed)
__device__ __align__(16) __half g_xh[16384ull * 1024];
__device__ __align__(16) __half g_Bqv[2048ull * 1024];
__device__ __align__(16) __half g_qv[16384ull * 2048];
__device__ __align__(16) float  g_gq[64 * 64];
__device__ __align__(16) __half g_wekt[128ull * 1024];
__device__ __align__(16) float  g_Lp[16384ull * 128];
__device__ __align__(16) float  g_poolv[128ull * 16 * 1024];
__device__ __align__(16) float  g_poolms[4096];
__device__ __align__(16) __half g_wrp[64ull * 4096];
__device__ __align__(16) __half g_B3[1024ull * 1024];
__device__ __align__(16) __half g_A3[16384ull * 1024];

// side stream + events, created at load time
static cudaStream_t g_s1;
static cudaEvent_t g_eA, g_ePW, g_eV;
static struct StreamInit {
    StreamInit() {
        cudaStreamCreateWithFlags(&g_s1, cudaStreamNonBlocking);
        cudaEventCreateWithFlags(&g_eA, cudaEventDisableTiming);
        cudaEventCreateWithFlags(&g_ePW, cudaEventDisableTiming);
        cudaEventCreateWithFlags(&g_eV, cudaEventDisableTiming);
    }
} g_stream_init;

__device__ __forceinline__ uint32_t smem_u32(const void* p) {
    uint32_t a;
    asm("{ .reg .u64 t; cvta.to.shared.u64 t, %1; cvt.u32.u64 %0, t; }" : "=r"(a) : "l"(p));
    return a;
}
__device__ __forceinline__ void cp16(uint32_t dst, const void* src) {
    asm volatile("cp.async.cg.shared.global [%0], [%1], 16;\n" :: "r"(dst), "l"(src));
}
__device__ __forceinline__ void mma16816h(float* c, const uint32_t* a, const uint32_t* b) {
    asm volatile(
        "mma.sync.aligned.m16n8k16.row.col.f32.f16.f16.f32 "
        "{%0,%1,%2,%3}, {%4,%5,%6,%7}, {%8,%9}, {%0,%1,%2,%3};"
        : "+f"(c[0]), "+f"(c[1]), "+f"(c[2]), "+f"(c[3])
        : "r"(a[0]), "r"(a[1]), "r"(a[2]), "r"(a[3]), "r"(b[0]), "r"(b[1]));
}

// ---------------------------------------------------------------------------
// mma.sync fp16 GEMM (byte-identical to R12)
// ---------------------------------------------------------------------------
#define BK_BYTES 128
#define ROWB 144
#define STAGE_B (128 * ROWB)
#define STAGES 3

template <bool HALF_OUT>
__global__ void __launch_bounds__(256, 2) gemm_mma(
    const void* __restrict__ Av, const void* __restrict__ Bv,
    const float* __restrict__ bias, void* __restrict__ Cv, int Kp, int Ntot)
{
    extern __shared__ char dsm[];
    const uint32_t aoff = smem_u32(dsm);
    const uint32_t boff = aoff + STAGES * STAGE_B;

    const int tid = threadIdx.x, wid = tid >> 5, lane = tid & 31;
    const int m0 = blockIdx.y << 7, n0 = blockIdx.x << 7;
    const int warp_m = (wid & 1) << 6;
    const int warp_n = (wid >> 1) << 5;

    const size_t KpB = (size_t)Kp * 2;
    const int nch = Kp >> 6;

    const int lr = tid >> 3;
    const int lc = (tid & 7) << 4;
    const char* Ag = (const char*)Av + (size_t)(m0 + lr) * KpB + lc;
    const char* Bg = (const char*)Bv + (size_t)(n0 + lr) * KpB + lc;
    const uint32_t Asw = aoff + (uint32_t)lr * ROWB + lc;
    const uint32_t Bsw = boff + (uint32_t)lr * ROWB + lc;

#define ISSUE(c, s) do {                                                      \
    size_t kb_ = (size_t)(c) * BK_BYTES;                                      \
    uint32_t so_ = (uint32_t)(s) * STAGE_B;                                   \
    _Pragma("unroll")                                                         \
    for (int i_ = 0; i_ < 4; i_++) {                                          \
        cp16(Asw + so_ + i_ * 32 * ROWB, Ag + kb_ + (size_t)i_ * 32 * KpB);   \
        cp16(Bsw + so_ + i_ * 32 * ROWB, Bg + kb_ + (size_t)i_ * 32 * KpB);   \
    }                                                                         \
    asm volatile("cp.async.commit_group;");                                   \
} while (0)

    float acc[4][4][4];
#pragma unroll
    for (int i = 0; i < 4; i++)
#pragma unroll
        for (int j = 0; j < 4; j++)
#pragma unroll
            for (int e = 0; e < 4; e++) acc[i][j][e] = 0.f;

    ISSUE(0, 0);
    ISSUE(1, 1);

    const int fr = lane & 15;
    const uint32_t fk = (lane & 16) ? 16u : 0u;

    for (int c = 0; c < nch; c++) {
        const int s = c % STAGES;
        if (c + 2 < nch) { asm volatile("cp.async.wait_group 1;"); }
        else             { asm volatile("cp.async.wait_group 0;"); }
        __syncthreads();
        if (c + 2 < nch) ISSUE(c + 2, (c + 2) % STAGES);

        const uint32_t as_ = aoff + (uint32_t)s * STAGE_B;
        const uint32_t bs_ = boff + (uint32_t)s * STAGE_B;

#pragma unroll
        for (int ks = 0; ks < 4; ks++) {
            const uint32_t kb = (uint32_t)ks * 32u + fk;
            uint32_t a[4][4], b[4][2];
#pragma unroll
            for (int mt = 0; mt < 4; mt++) {
                uint32_t addr = as_ + (uint32_t)(warp_m + mt * 16 + fr) * ROWB + kb;
                asm volatile("ldmatrix.sync.aligned.m8n8.x4.shared.b16 {%0,%1,%2,%3}, [%4];"
                             : "=r"(a[mt][0]), "=r"(a[mt][1]), "=r"(a[mt][2]), "=r"(a[mt][3])
                             : "r"(addr));
            }
#pragma unroll
            for (int nb = 0; nb < 2; nb++) {
                uint32_t addr = bs_ + (uint32_t)(warp_n + nb * 16 + fr) * ROWB + kb;
                uint32_t r0, r1, r2, r3;
                asm volatile("ldmatrix.sync.aligned.m8n8.x4.shared.b16 {%0,%1,%2,%3}, [%4];"
                             : "=r"(r0), "=r"(r1), "=r"(r2), "=r"(r3) : "r"(addr));
                b[nb * 2][0] = r0; b[nb * 2][1] = r2;
                b[nb * 2 + 1][0] = r1; b[nb * 2 + 1][1] = r3;
            }
#pragma unroll
            for (int mt = 0; mt < 4; mt++)
#pragma unroll
                for (int nt = 0; nt < 4; nt++)
                    mma16816h(acc[mt][nt], a[mt], b[nt]);
        }
    }

#pragma unroll
    for (int nt = 0; nt < 4; nt++) {
        const int n = n0 + warp_n + nt * 8 + ((lane & 3) << 1);
        float bx = 0.f, by = 0.f;
        if (!HALF_OUT && bias) { float2 bb = *(const float2*)(bias + n); bx = bb.x; by = bb.y; }
#pragma unroll
        for (int mt = 0; mt < 4; mt++) {
            const int m = m0 + warp_m + mt * 16 + (lane >> 2);
            if (HALF_OUT) {
                __half* Ch = (__half*)Cv;
                *(__half2*)(Ch + (size_t)m * Ntot + n) =
                    __floats2half2_rn(acc[mt][nt][0], acc[mt][nt][1]);
                *(__half2*)(Ch + (size_t)(m + 8) * Ntot + n) =
                    __floats2half2_rn(acc[mt][nt][2], acc[mt][nt][3]);
            } else {
                float* Cf = (float*)Cv;
                float2 v0 = {acc[mt][nt][0] + bx, acc[mt][nt][1] + by};
                float2 v1 = {acc[mt][nt][2] + bx, acc[mt][nt][3] + by};
                *(float2*)(Cf + (size_t)m * Ntot + n) = v0;
                *(float2*)(Cf + (size_t)(m + 8) * Ntot + n) = v1;
            }
        }
    }
#undef ISSUE
}

// x[M,1024] fp32 -> xh fp16
__global__ void __launch_bounds__(256) conv_x_kernel(
    const float* __restrict__ x, __half* __restrict__ outh)
{
    size_t g = ((size_t)blockIdx.x * 256 + threadIdx.x) * 4;
    float4 v = *(const float4*)(x + g);
    __half2* q = (__half2*)(outh + g);
    q[0] = __floats2half2_rn(v.x, v.y);
    q[1] = __floats2half2_rn(v.z, v.w);
}

// 3-job weight transpose+convert
__global__ void __launch_bounds__(256) conv_w3_kernel(
    const float* __restrict__ W_qkv, const float* __restrict__ W_out,
    __half* __restrict__ Bqv, __half* __restrict__ B3)
{
    __shared__ float t[32][33];
    const int z = blockIdx.z;
    const float* W = (z == 2) ? W_out : W_qkv;
    const int srcN = (z == 2) ? 1024 : 3072;
    const int coff = (z == 1) ? 2048 : 0;
    __half* out = (z == 0) ? Bqv : (z == 1) ? (Bqv + 1024ull * 1024) : B3;

    int n0 = blockIdx.x * 32, k0 = blockIdx.y * 32;
    int tx = threadIdx.x, ty = threadIdx.y;
    for (int i = ty; i < 32; i += 8) t[i][tx] = W[(size_t)(k0 + i) * srcN + coff + n0 + tx];
    __syncthreads();
    for (int i = ty; i < 32; i += 8)
        out[(size_t)(n0 + i) * 1024 + k0 + tx] = __float2half(t[tx][i]);
}

// we_q rows: wekt[h][i] = (W_q_h @ (w_q*SCALE))[i] * WSCALE; rows 16..127 zero
__global__ void __launch_bounds__(256) prep_weq_kernel(
    const float* __restrict__ W_qkv, const float* __restrict__ w_q,
    __half* __restrict__ wekt)
{
    const int bh = blockIdx.x, tid = threadIdx.x;
    if (bh >= 16) {
        for (int i = tid; i < 1024; i += 256)
            wekt[(size_t)bh * 1024 + i] = __float2half(0.f);
        return;
    }
    __shared__ float s_wq[64];
    if (tid < 64) s_wq[tid] = w_q[tid] * SCALE;
    __syncthreads();
    for (int i = tid; i < 1024; i += 256) {
        const float* wrow = W_qkv + (size_t)i * 3072 + bh * 64;
        float s = 0.f;
#pragma unroll
        for (int d = 0; d < 64; d++) s = fmaf(wrow[d], s_wq[d], s);
        wekt[(size_t)bh * 1024 + i] = __float2half(s * WSCALE);
    }
}

// flash partial pooling of x with softmax weights from Lp.
// perb=0: logit column = h (q pass); perb=1: column = b*16+h (k pass).
__global__ void __launch_bounds__(256) poolx2_kernel(
    const __half* __restrict__ xh, const float* __restrict__ Lp,
    const unsigned char* __restrict__ mask,
    float* __restrict__ poolv, float* __restrict__ poolms, int N, int perb)
{
    const int blk = blockIdx.x;
    const int dh = blk & 1;
    const int bp = blk >> 1;
    const int b = bp >> 5, part = bp & 31;
    const int rows = N / 32;   // 128
    const int n0 = part * rows;
    const int tid = threadIdx.x;

    __shared__ float sl[128 * 16];
    __shared__ float sms[16 * 16 * 2];
    __shared__ float smh[16];

    const size_t row0 = (size_t)b * N + n0;
    const int col0 = perb ? b * 16 : 0;

    if (tid < 128) {
        const float* lrow = Lp + (row0 + tid) * 128 + col0;
        bool mk = mask[row0 + tid] != 0;
#pragma unroll
        for (int h = 0; h < 16; h++)
            sl[tid * 16 + h] = mk ? lrow[h] * (1.0f / WSCALE) : -1e30f;
    }
    __syncthreads();
    {
        const int seg = tid >> 4, h = tid & 15;
        float m = -1e30f;
#pragma unroll
        for (int r = 0; r < 8; r++) m = fmaxf(m, sl[(seg * 8 + r) * 16 + h]);
        float s = 0.f;
#pragma unroll
        for (int r = 0; r < 8; r++) s += __expf(sl[(seg * 8 + r) * 16 + h] - m);
        sms[(seg * 16 + h) * 2] = m;
        sms[(seg * 16 + h) * 2 + 1] = s;
    }
    __syncthreads();
    if (tid < 16) {
        float m = -1e30f;
#pragma unroll
        for (int g = 0; g < 16; g++) m = fmaxf(m, sms[(g * 16 + tid) * 2]);
        float s = 0.f;
#pragma unroll
        for (int g = 0; g < 16; g++)
            s += sms[(g * 16 + tid) * 2 + 1] * __expf(sms[(g * 16 + tid) * 2] - m);
        smh[tid] = m;
        if (dh == 0) {
            poolms[(bp * 16 + tid) * 2] = m;
            poolms[(bp * 16 + tid) * 2 + 1] = s;
        }
    }
    __syncthreads();
    for (int i = tid; i < 128 * 16; i += 256)
        sl[i] = __expf(sl[i] - smh[i & 15]);
    __syncthreads();

    const __half2* xp = (const __half2*)(xh + row0 * 1024) + dh * 256 + tid;
    float accx[16], accy[16];
#pragma unroll
    for (int h = 0; h < 16; h++) { accx[h] = 0.f; accy[h] = 0.f; }
    for (int n = 0; n < 128; n++) {
        float2 f = __half22float2(xp[(size_t)n * 512]);
        const float* pn = &sl[n * 16];
#pragma unroll
        for (int h = 0; h < 16; h++) {
            float p = pn[h];
            accx[h] = fmaf(p, f.x, accx[h]);
            accy[h] = fmaf(p, f.y, accy[h]);
        }
    }
#pragma unroll
    for (int h = 0; h < 16; h++) {
        float2 o = {accx[h], accy[h]};
        *(float2*)(poolv + ((size_t)(bp * 16 + h) << 10) + dh * 512 + tid * 2) = o;
    }
}

// q pass merge: pooled_xq -> gq = pooled@W_q; vk = gq*wk*SCALE; wekt = W_k@vk
__global__ void __launch_bounds__(256) combine_gq_wek_kernel(
    const float* __restrict__ poolv, const float* __restrict__ poolms,
    const float* __restrict__ W_qkv, const float* __restrict__ w_k,
    float* __restrict__ gq, __half* __restrict__ wekt)
{
    const int bh = blockIdx.x, b = bh >> 4, h = bh & 15;
    const int tid = threadIdx.x;
    __shared__ float wp[32];
    __shared__ float pooled[1024];
    __shared__ float red[256];
    __shared__ float s_vk[64];
    __shared__ float sM;

    if (tid == 0) {
        float M = -1e30f;
        for (int p = 0; p < 32; p++) M = fmaxf(M, poolms[((b * 32 + p) * 16 + h) * 2]);
        sM = M;
    }
    __syncthreads();
    if (tid < 32) {
        float e = __expf(poolms[((b * 32 + tid) * 16 + h) * 2] - sM);
        float se = poolms[((b * 32 + tid) * 16 + h) * 2 + 1] * e;
        float S = se;
#pragma unroll
        for (int o = 16; o; o >>= 1) S += __shfl_xor_sync(0xffffffffu, S, o);
        wp[tid] = e / S;
    }
    __syncthreads();

    for (int i = tid; i < 1024; i += 256) {
        float s = 0.f;
#pragma unroll
        for (int p = 0; p < 32; p++)
            s = fmaf(poolv[((size_t)((b * 32 + p) * 16 + h) << 10) + i], wp[p], s);
        pooled[i] = s;
    }
    __syncthreads();

    const int d = tid & 63, seg = tid >> 6;
    float a = 0.f;
    const float* wcol = W_qkv + h * 64 + d;     // q columns (offset 0)
    for (int i = seg * 256; i < seg * 256 + 256; i++)
        a = fmaf(pooled[i], wcol[(size_t)i * 3072], a);
    red[tid] = a;
    __syncthreads();
    if (tid < 64) {
        float g = red[tid] + red[tid + 64] + red[tid + 128] + red[tid + 192];
        gq[bh * 64 + tid] = g;
        s_vk[tid] = g * w_k[tid] * SCALE;
    }
    __syncthreads();

    for (int i = tid; i < 1024; i += 256) {
        const float* wrow = W_qkv + (size_t)i * 3072 + 1024 + h * 64;
        float s = 0.f;
#pragma unroll
        for (int dd = 0; dd < 64; dd++) s = fmaf(wrow[dd], s_vk[dd], s);
        wekt[(size_t)bh * 1024 + i] = __float2half(s * WSCALE);
    }
}

// k pass merge: pooled_xk -> gk = gq * (pooled@W_k); wrp = diag(gk)*W_r
__global__ void __launch_bounds__(256) combinek_wrp_kernel(
    const float* __restrict__ poolv, const float* __restrict__ poolms,
    const float* __restrict__ W_qkv, const float* __restrict__ gq,
    const float* __restrict__ W_r, __half* __restrict__ wrp)
{
    const int bh = blockIdx.x, b = bh >> 4, h = bh & 15;
    const int tid = threadIdx.x;
    __shared__ float wp[32];
    __shared__ float pooled[1024];
    __shared__ float red[256];
    __shared__ float s_gk[64];
    __shared__ float sM;

    if (tid == 0) {
        float M = -1e30f;
        for (int p = 0; p < 32; p++) M = fmaxf(M, poolms[((b * 32 + p) * 16 + h) * 2]);
        sM = M;
    }
    __syncthreads();
    if (tid < 32) {
        float e = __expf(poolms[((b * 32 + tid) * 16 + h) * 2] - sM);
        float se = poolms[((b * 32 + tid) * 16 + h) * 2 + 1] * e;
        float S = se;
#pragma unroll
        for (int o = 16; o; o >>= 1) S += __shfl_xor_sync(0xffffffffu, S, o);
        wp[tid] = e / S;
    }
    __syncthreads();

    for (int i = tid; i < 1024; i += 256) {
        float s = 0.f;
#pragma unroll
        for (int p = 0; p < 32; p++)
            s = fmaf(poolv[((size_t)((b * 32 + p) * 16 + h) << 10) + i], wp[p], s);
        pooled[i] = s;
    }
    __syncthreads();

    const int d = tid & 63, seg = tid >> 6;
    float a = 0.f;
    const float* wcol = W_qkv + 1024 + h * 64 + d;
    for (int i = seg * 256; i < seg * 256 + 256; i++)
        a = fmaf(pooled[i], wcol[(size_t)i * 3072], a);
    red[tid] = a;
    __syncthreads();
    if (tid < 64) {
        float t = red[tid] + red[tid + 64] + red[tid + 128] + red[tid + 192];
        s_gk[tid] = gq[bh * 64 + tid] * t;
    }
    __syncthreads();

    for (int i = tid; i < 4096; i += 256) {
        int e = i >> 6, dd = i & 63;
        wrp[(size_t)bh * 4096 + i] = __float2half(s_gk[dd] * W_r[dd * 64 + e]);
    }
}

// rgemm: r = v_h @ wrp_bh + q + b_r -> A3 fp16.
__global__ void __launch_bounds__(256) rgemm_kernel(
    const __half* __restrict__ qv, const __half* __restrict__ wrp,
    const float* __restrict__ b_r, __half* __restrict__ A3, int N)
{
    const int h = blockIdx.x;
    const size_t row0 = (size_t)blockIdx.y * 128;
    const int b = (int)(row0 >> 12);
    const int bh = b * 16 + h;
    const int tid = threadIdx.x, wid = tid >> 5, lane = tid & 31;

    __shared__ __half sA[128 * 72];
    __shared__ __half sB[64 * 72];
    __shared__ float sbr[64];

#pragma unroll
    for (int i = 0; i < 4; i++) {
        int idx = tid + i * 256;
        int r = idx >> 3, c = (idx & 7) << 3;
        *(uint4*)(&sA[r * 72 + c]) =
            *(const uint4*)(qv + (row0 + r) * 2048 + 1024 + h * 64 + c);
    }
#pragma unroll
    for (int i = 0; i < 2; i++) {
        int idx = tid + i * 256;
        int r = idx >> 3, c = (idx & 7) << 3;
        *(uint4*)(&sB[r * 72 + c]) =
            *(const uint4*)(wrp + (size_t)bh * 4096 + r * 64 + c);
    }
    if (tid < 64) sbr[tid] = b_r[tid];
    __syncthreads();

    const uint32_t smA = smem_u32(sA), smB = smem_u32(sB);
    const int fr = lane & 15;
    const uint32_t fk = (lane & 16) ? 16u : 0u;

    float acc[8][4];
#pragma unroll
    for (int nt = 0; nt < 8; nt++)
#pragma unroll
        for (int e = 0; e < 4; e++) acc[nt][e] = 0.f;

#pragma unroll
    for (int ks = 0; ks < 4; ks++) {
        const uint32_t kb = (uint32_t)ks * 32u + fk;
        uint32_t a[4], bfr[8][2];
        {
            uint32_t addr = smA + (uint32_t)(wid * 16 + fr) * 144 + kb;
            asm volatile("ldmatrix.sync.aligned.m8n8.x4.shared.b16 {%0,%1,%2,%3}, [%4];"
                         : "=r"(a[0]), "=r"(a[1]), "=r"(a[2]), "=r"(a[3]) : "r"(addr));
        }
#pragma unroll
        for (int nb = 0; nb < 4; nb++) {
            uint32_t addr = smB + (uint32_t)(nb * 16 + fr) * 144 + kb;
            uint32_t r0, r1, r2, r3;
            asm volatile("ldmatrix.sync.aligned.m8n8.x4.shared.b16 {%0,%1,%2,%3}, [%4];"
                         : "=r"(r0), "=r"(r1), "=r"(r2), "=r"(r3) : "r"(addr));
            bfr[nb * 2][0] = r0; bfr[nb * 2][1] = r2;
            bfr[nb * 2 + 1][0] = r1; bfr[nb * 2 + 1][1] = r3;
        }
#pragma unroll
        for (int nt = 0; nt < 8; nt++)
            mma16816h(acc[nt], a, bfr[nt]);
    }

    const int r0o = wid * 16 + (lane >> 2);
#pragma unroll
    for (int nt = 0; nt < 8; nt++) {
        const int col = nt * 8 + ((lane & 3) << 1);
        float brx = sbr[col], bry = sbr[col + 1];
        const size_t rA = row0 + r0o, rB = row0 + r0o + 8;
        float2 qa = __half22float2(*(const __half2*)(qv + rA * 2048 + h * 64 + col));
        float2 qb = __half22float2(*(const __half2*)(qv + rB * 2048 + h * 64 + col));
        *(__half2*)(A3 + rA * 1024 + h * 64 + col) =
            __floats2half2_rn(acc[nt][0] + brx + qa.x, acc[nt][1] + bry + qa.y);
        *(__half2*)(A3 + rB * 1024 + h * 64 + col) =
            __floats2half2_rn(acc[nt][2] + brx + qb.x, acc[nt][3] + bry + qb.y);
    }
}

extern "C" void kernel_launch(void* const* d_in, const int* in_sizes, int n_in,
                              void* d_out, int out_size)
{
    const float*         x     = (const float*)d_in[0];
    const unsigned char* mask  = (const unsigned char*)d_in[1];
    const float*         W_qkv = (const float*)d_in[2];
    const float*         w_q   = (const float*)d_in[3];
    const float*         w_k   = (const float*)d_in[4];
    const float*         W_r   = (const float*)d_in[5];
    const float*         b_r   = (const float*)d_in[6];
    const float*         W_out = (const float*)d_in[7];
    const float*         b_out = (const float*)d_in[8];
    float* out = (float*)d_out;

    const int M = in_sizes[0] / 1024;   // 16384
    const int N = M / 4;                // 4096

    __half *xh, *Bqv, *qv, *wekt, *wrp, *B3, *A3;
    float *gq, *Lp, *poolv, *poolms;
    cudaGetSymbolAddress((void**)&xh, g_xh);
    cudaGetSymbolAddress((void**)&Bqv, g_Bqv);
    cudaGetSymbolAddress((void**)&qv, g_qv);
    cudaGetSymbolAddress((void**)&gq, g_gq);
    cudaGetSymbolAddress((void**)&wekt, g_wekt);
    cudaGetSymbolAddress((void**)&Lp, g_Lp);
    cudaGetSymbolAddress((void**)&poolv, g_poolv);
    cudaGetSymbolAddress((void**)&poolms, g_poolms);
    cudaGetSymbolAddress((void**)&wrp, g_wrp);
    cudaGetSymbolAddress((void**)&B3, g_B3);
    cudaGetSymbolAddress((void**)&A3, g_A3);

    const int SMEM = STAGES * STAGE_B * 2;  // 110592
    cudaFuncSetAttribute(gemm_mma<true>,  cudaFuncAttributeMaxDynamicSharedMemorySize, SMEM);
    cudaFuncSetAttribute(gemm_mma<false>, cudaFuncAttributeMaxDynamicSharedMemorySize, SMEM);

    // main: conv_x (xh needed by both streams)
    conv_x_kernel<<<M, 256>>>(x, xh);
    cudaEventRecord(g_eA, 0);

    // side: conv_w3 + prep_weq (weights only), then GEMM1 q+v after xh ready
    cudaStreamWaitEvent(g_s1, g_eA, 0);
    conv_w3_kernel<<<dim3(32, 32, 3), dim3(32, 8), 0, g_s1>>>(W_qkv, W_out, Bqv, B3);
    prep_weq_kernel<<<128, 256, 0, g_s1>>>(W_qkv, w_q, wekt);
    cudaEventRecord(g_ePW, g_s1);
    gemm_mma<true><<<dim3(16, 128), 256, SMEM, g_s1>>>(xh, Bqv, nullptr, qv, 1024, 2048);
    cudaEventRecord(g_eV, g_s1);

    // main mid chain (depends only on xh + weights)
    cudaStreamWaitEvent(0, g_ePW, 0);
    gemm_mma<false><<<dim3(1, 128), 256, SMEM>>>(xh, wekt, nullptr, Lp, 1024, 128);
    poolx2_kernel<<<256, 256>>>(xh, Lp, mask, poolv, poolms, N, 0);
    combine_gq_wek_kernel<<<64, 256>>>(poolv, poolms, W_qkv, w_k, gq, wekt);
    gemm_mma<false><<<dim3(1, 128), 256, SMEM>>>(xh, wekt, nullptr, Lp, 1024, 128);
    poolx2_kernel<<<256, 256>>>(xh, Lp, mask, poolv, poolms, N, 1);
    combinek_wrp_kernel<<<64, 256>>>(poolv, poolms, W_qkv, gq, W_r, wrp);

    // join: q,v ready
    cudaStreamWaitEvent(0, g_eV, 0);

    // r = v @ (diag(gk)W_r) + q + b_r -> fp16
    rgemm_kernel<<<dim3(16, M / 128), 256>>>(qv, wrp, b_r, A3, N);

    // out = r @ W_out + b_out
    gemm_mma<false><<<dim3(8, 128), 256, SMEM>>>(A3, B3, b_out, out, 1024, 1024);
}

// round 16
// speedup vs baseline: 1.1183x; 1.1183x over previous
#include <cuda_runtime.h>
#include <cuda_fp16.h>
#include <cfloat>
#include <cstdint>

#define HEADS 16
#define DH 64
#define SCALE 0.125f
#define PARTS 8
#define PSTRIDE 68
#define WSCALE 16384.0f

// scratch (__device__ globals; no cudaMalloc allowed)
__device__ __align__(16) __half g_xh[16384ull * 1024];
__device__ __align__(16) __half g_Bqv[2048ull * 1024];
__device__ __align__(16) __half g_qv[16384ull * 2048];
__device__ __align__(16) float  g_part[64 * PARTS * PSTRIDE];
__device__ __align__(16) float  g_gq[64 * 64];
__device__ __align__(16) float  g_vk[64 * 64];
__device__ __align__(16) __half g_wekt[128ull * 1024];
__device__ __align__(16) float  g_Lp[16384ull * 128];
__device__ __align__(16) float  g_poolv[128ull * 16 * 1024];
__device__ __align__(16) float  g_poolms[4096];
__device__ __align__(16) __half g_wrp[64ull * 4096];
__device__ __align__(16) __half g_B3[1024ull * 1024];
__device__ __align__(16) __half g_A3[16384ull * 1024];

// side stream + events, created at load time
static cudaStream_t g_s1;
static cudaEvent_t g_e0, g_e1;
static struct StreamInit {
    StreamInit() {
        cudaStreamCreateWithFlags(&g_s1, cudaStreamNonBlocking);
        cudaEventCreateWithFlags(&g_e0, cudaEventDisableTiming);
        cudaEventCreateWithFlags(&g_e1, cudaEventDisableTiming);
    }
} g_stream_init;

__device__ __forceinline__ uint32_t smem_u32(const void* p) {
    uint32_t a;
    asm("{ .reg .u64 t; cvta.to.shared.u64 t, %1; cvt.u32.u64 %0, t; }" : "=r"(a) : "l"(p));
    return a;
}
__device__ __forceinline__ void cp16(uint32_t dst, const void* src) {
    asm volatile("cp.async.cg.shared.global [%0], [%1], 16;\n" :: "r"(dst), "l"(src));
}
__device__ __forceinline__ void mma16816h(float* c, const uint32_t* a, const uint32_t* b) {
    asm volatile(
        "mma.sync.aligned.m16n8k16.row.col.f32.f16.f16.f32 "
        "{%0,%1,%2,%3}, {%4,%5,%6,%7}, {%8,%9}, {%0,%1,%2,%3};"
        : "+f"(c[0]), "+f"(c[1]), "+f"(c[2]), "+f"(c[3])
        : "r"(a[0]), "r"(a[1]), "r"(a[2]), "r"(a[3]), "r"(b[0]), "r"(b[1]));
}

// ---------------------------------------------------------------------------
// mma.sync fp16 GEMM (byte-identical to R10-R12)
// ---------------------------------------------------------------------------
#define BK_BYTES 128
#define ROWB 144
#define STAGE_B (128 * ROWB)
#define STAGES 3

template <bool HALF_OUT>
__global__ void __launch_bounds__(256, 2) gemm_mma(
    const void* __restrict__ Av, const void* __restrict__ Bv,
    const float* __restrict__ bias, void* __restrict__ Cv, int Kp, int Ntot)
{
    extern __shared__ char dsm[];
    const uint32_t aoff = smem_u32(dsm);
    const uint32_t boff = aoff + STAGES * STAGE_B;

    const int tid = threadIdx.x, wid = tid >> 5, lane = tid & 31;
    const int m0 = blockIdx.y << 7, n0 = blockIdx.x << 7;
    const int warp_m = (wid & 1) << 6;
    const int warp_n = (wid >> 1) << 5;

    const size_t KpB = (size_t)Kp * 2;
    const int nch = Kp >> 6;

    const int lr = tid >> 3;
    const int lc = (tid & 7) << 4;
    const char* Ag = (const char*)Av + (size_t)(m0 + lr) * KpB + lc;
    const char* Bg = (const char*)Bv + (size_t)(n0 + lr) * KpB + lc;
    const uint32_t Asw = aoff + (uint32_t)lr * ROWB + lc;
    const uint32_t Bsw = boff + (uint32_t)lr * ROWB + lc;

#define ISSUE(c, s) do {                                                      \
    size_t kb_ = (size_t)(c) * BK_BYTES;                                      \
    uint32_t so_ = (uint32_t)(s) * STAGE_B;                                   \
    _Pragma("unroll")                                                         \
    for (int i_ = 0; i_ < 4; i_++) {                                          \
        cp16(Asw + so_ + i_ * 32 * ROWB, Ag + kb_ + (size_t)i_ * 32 * KpB);   \
        cp16(Bsw + so_ + i_ * 32 * ROWB, Bg + kb_ + (size_t)i_ * 32 * KpB);   \
    }                                                                         \
    asm volatile("cp.async.commit_group;");                                   \
} while (0)

    float acc[4][4][4];
#pragma unroll
    for (int i = 0; i < 4; i++)
#pragma unroll
        for (int j = 0; j < 4; j++)
#pragma unroll
            for (int e = 0; e < 4; e++) acc[i][j][e] = 0.f;

    ISSUE(0, 0);
    ISSUE(1, 1);

    const int fr = lane & 15;
    const uint32_t fk = (lane & 16) ? 16u : 0u;

    for (int c = 0; c < nch; c++) {
        const int s = c % STAGES;
        if (c + 2 < nch) { asm volatile("cp.async.wait_group 1;"); }
        else             { asm volatile("cp.async.wait_group 0;"); }
        __syncthreads();
        if (c + 2 < nch) ISSUE(c + 2, (c + 2) % STAGES);

        const uint32_t as_ = aoff + (uint32_t)s * STAGE_B;
        const uint32_t bs_ = boff + (uint32_t)s * STAGE_B;

#pragma unroll
        for (int ks = 0; ks < 4; ks++) {
            const uint32_t kb = (uint32_t)ks * 32u + fk;
            uint32_t a[4][4], b[4][2];
#pragma unroll
            for (int mt = 0; mt < 4; mt++) {
                uint32_t addr = as_ + (uint32_t)(warp_m + mt * 16 + fr) * ROWB + kb;
                asm volatile("ldmatrix.sync.aligned.m8n8.x4.shared.b16 {%0,%1,%2,%3}, [%4];"
                             : "=r"(a[mt][0]), "=r"(a[mt][1]), "=r"(a[mt][2]), "=r"(a[mt][3])
                             : "r"(addr));
            }
#pragma unroll
            for (int nb = 0; nb < 2; nb++) {
                uint32_t addr = bs_ + (uint32_t)(warp_n + nb * 16 + fr) * ROWB + kb;
                uint32_t r0, r1, r2, r3;
                asm volatile("ldmatrix.sync.aligned.m8n8.x4.shared.b16 {%0,%1,%2,%3}, [%4];"
                             : "=r"(r0), "=r"(r1), "=r"(r2), "=r"(r3) : "r"(addr));
                b[nb * 2][0] = r0; b[nb * 2][1] = r2;
                b[nb * 2 + 1][0] = r1; b[nb * 2 + 1][1] = r3;
            }
#pragma unroll
            for (int mt = 0; mt < 4; mt++)
#pragma unroll
                for (int nt = 0; nt < 4; nt++)
                    mma16816h(acc[mt][nt], a[mt], b[nt]);
        }
    }

#pragma unroll
    for (int nt = 0; nt < 4; nt++) {
        const int n = n0 + warp_n + nt * 8 + ((lane & 3) << 1);
        float bx = 0.f, by = 0.f;
        if (!HALF_OUT && bias) { float2 bb = *(const float2*)(bias + n); bx = bb.x; by = bb.y; }
#pragma unroll
        for (int mt = 0; mt < 4; mt++) {
            const int m = m0 + warp_m + mt * 16 + (lane >> 2);
            if (HALF_OUT) {
                __half* Ch = (__half*)Cv;
                *(__half2*)(Ch + (size_t)m * Ntot + n) =
                    __floats2half2_rn(acc[mt][nt][0], acc[mt][nt][1]);
                *(__half2*)(Ch + (size_t)(m + 8) * Ntot + n) =
                    __floats2half2_rn(acc[mt][nt][2], acc[mt][nt][3]);
            } else {
                float* Cf = (float*)Cv;
                float2 v0 = {acc[mt][nt][0] + bx, acc[mt][nt][1] + by};
                float2 v1 = {acc[mt][nt][2] + bx, acc[mt][nt][3] + by};
                *(float2*)(Cf + (size_t)m * Ntot + n) = v0;
                *(float2*)(Cf + (size_t)(m + 8) * Ntot + n) = v1;
            }
        }
    }
#undef ISSUE
}

// x[M,1024] fp32 -> xh fp16
__global__ void __launch_bounds__(256) conv_x_kernel(
    const float* __restrict__ x, __half* __restrict__ outh)
{
    size_t g = ((size_t)blockIdx.x * 256 + threadIdx.x) * 4;
    float4 v = *(const float4*)(x + g);
    __half2* q = (__half2*)(outh + g);
    q[0] = __floats2half2_rn(v.x, v.y);
    q[1] = __floats2half2_rn(v.z, v.w);
}

// 3-job weight transpose+convert
__global__ void __launch_bounds__(256) conv_w3_kernel(
    const float* __restrict__ W_qkv, const float* __restrict__ W_out,
    __half* __restrict__ Bqv, __half* __restrict__ B3)
{
    __shared__ float t[32][33];
    const int z = blockIdx.z;
    const float* W = (z == 2) ? W_out : W_qkv;
    const int srcN = (z == 2) ? 1024 : 3072;
    const int coff = (z == 1) ? 2048 : 0;
    __half* out = (z == 0) ? Bqv : (z == 1) ? (Bqv + 1024ull * 1024) : B3;

    int n0 = blockIdx.x * 32, k0 = blockIdx.y * 32;
    int tx = threadIdx.x, ty = threadIdx.y;
    for (int i = ty; i < 32; i += 8) t[i][tx] = W[(size_t)(k0 + i) * srcN + coff + n0 + tx];
    __syncthreads();
    for (int i = ty; i < 32; i += 8)
        out[(size_t)(n0 + i) * 1024 + k0 + tx] = __float2half(t[tx][i]);
}

// q-pass partial softmax-pooling (PARTS=8), LDG.128 loads
__global__ void __launch_bounds__(256) mid_part_q(
    const __half* __restrict__ qv, const unsigned char* __restrict__ mask,
    const float* __restrict__ w_q, float* __restrict__ partials, int N)
{
    const int bh = blockIdx.x / PARTS, part = blockIdx.x % PARTS;
    const int b = bh >> 4, h = bh & 15;
    const int tid = threadIdx.x, lane = tid & 31, wid = tid >> 5;
    const int rows = N / PARTS;
    const int nbase = part * rows;

    __shared__ float s_l[512];
    __shared__ float s_vec[64];
    __shared__ float s_red[8];
    __shared__ float s_acc[8][64];
    __shared__ float s_m;

    const __half* base = qv + ((size_t)b * N + nbase) * 2048 + h * DH;
    const unsigned char* mrow = mask + (size_t)b * N + nbase;

    if (tid < 64) s_vec[tid] = w_q[tid] * SCALE;
    __syncthreads();

    float lmax = -FLT_MAX;
    for (int i = tid; i < rows; i += 256) {
        const uint4* r4 = (const uint4*)(base + (size_t)i * 2048);
        float dot = 0.f;
#pragma unroll
        for (int u = 0; u < 8; u++) {
            uint4 t = r4[u];
            const __half2* hp = (const __half2*)&t;
#pragma unroll
            for (int j = 0; j < 4; j++) {
                float2 f = __half22float2(hp[j]);
                dot += f.x * s_vec[u * 8 + 2 * j] + f.y * s_vec[u * 8 + 2 * j + 1];
            }
        }
        float lg = mrow[i] ? dot : -FLT_MAX;
        s_l[i] = lg;
        lmax = fmaxf(lmax, lg);
    }
#pragma unroll
    for (int o = 16; o; o >>= 1) lmax = fmaxf(lmax, __shfl_xor_sync(~0u, lmax, o));
    if (lane == 0) s_red[wid] = lmax;
    __syncthreads();
    if (tid == 0) {
        float m = s_red[0];
        for (int i = 1; i < 8; i++) m = fmaxf(m, s_red[i]);
        s_m = m;
    }
    __syncthreads();
    const float m = s_m;

    float lsum = 0.f;
    float acc[DH];
#pragma unroll
    for (int d = 0; d < DH; d++) acc[d] = 0.f;
    for (int i = tid; i < rows; i += 256) {
        float p = __expf(s_l[i] - m);
        lsum += p;
        const uint4* r4 = (const uint4*)(base + (size_t)i * 2048);
#pragma unroll
        for (int u = 0; u < 8; u++) {
            uint4 t = r4[u];
            const __half2* hp = (const __half2*)&t;
#pragma unroll
            for (int j = 0; j < 4; j++) {
                float2 f = __half22float2(hp[j]);
                acc[u * 8 + 2 * j]     = fmaf(p, f.x, acc[u * 8 + 2 * j]);
                acc[u * 8 + 2 * j + 1] = fmaf(p, f.y, acc[u * 8 + 2 * j + 1]);
            }
        }
    }
#pragma unroll
    for (int o = 16; o; o >>= 1) lsum += __shfl_xor_sync(~0u, lsum, o);
#pragma unroll
    for (int d = 0; d < DH; d++) {
        float v = acc[d];
#pragma unroll
        for (int o = 16; o; o >>= 1) v += __shfl_xor_sync(~0u, v, o);
        if (lane == 0) s_acc[wid][d] = v;
    }
    __syncthreads();
    if (lane == 0) s_red[wid] = lsum;
    __syncthreads();

    float* po = partials + (size_t)(bh * PARTS + part) * PSTRIDE;
    if (tid == 0) {
        float s = 0.f;
        for (int i = 0; i < 8; i++) s += s_red[i];
        po[0] = m;
        po[1] = s;
    }
    if (tid < 64) {
        float v = 0.f;
#pragma unroll
        for (int w = 0; w < 8; w++) v += s_acc[w][tid];
        po[2 + tid] = v;
    }
}

// fused: merge q-pass partials -> gq, vk; then wekt rows for this bh.
__global__ void __launch_bounds__(256) combineq_wek_kernel(
    const float* __restrict__ partials, const float* __restrict__ w_k,
    const float* __restrict__ W_qkv,
    float* __restrict__ gq, float* __restrict__ vk, __half* __restrict__ wekt)
{
    const int bh = blockIdx.x, tid = threadIdx.x;
    if (bh >= 64) {
        for (int i = tid; i < 1024; i += 256)
            wekt[(size_t)bh * 1024 + i] = __float2half(0.f);
        return;
    }
    __shared__ float s_vk[64];
    if (tid < 64) {
        const int d = tid;
        const float* p = partials + (size_t)bh * PARTS * PSTRIDE;
        float m = -FLT_MAX;
#pragma unroll
        for (int i = 0; i < PARTS; i++) m = fmaxf(m, p[i * PSTRIDE]);
        float s = 0.f, v = 0.f;
#pragma unroll
        for (int i = 0; i < PARTS; i++) {
            float e = __expf(p[i * PSTRIDE] - m);
            s += p[i * PSTRIDE + 1] * e;
            v += p[i * PSTRIDE + 2 + d] * e;
        }
        float pooled = v / s;
        gq[bh * 64 + d] = pooled;
        float vkd = pooled * w_k[d] * SCALE;
        vk[bh * 64 + d] = vkd;
        s_vk[d] = vkd;
    }
    __syncthreads();
    const int h = bh & 15;
    for (int i = tid; i < 1024; i += 256) {
        const float* wrow = W_qkv + (size_t)i * 3072 + 1024 + h * 64;
        float s = 0.f;
#pragma unroll
        for (int d = 0; d < 64; d++) s = fmaf(wrow[d], s_vk[d], s);
        wekt[(size_t)bh * 1024 + i] = __float2half(s * WSCALE);
    }
}

// flash partial pooling of x with k-softmax weights (32 parts x 128 rows)
__global__ void __launch_bounds__(256) poolx2_kernel(
    const __half* __restrict__ xh, const float* __restrict__ Lp,
    const unsigned char* __restrict__ mask,
    float* __restrict__ poolv, float* __restrict__ poolms, int N)
{
    const int blk = blockIdx.x;
    const int dh = blk & 1;
    const int bp = blk >> 1;
    const int b = bp >> 5, part = bp & 31;
    const int rows = N / 32;
    const int n0 = part * rows;
    const int tid = threadIdx.x;

    __shared__ float sl[128 * 16];
    __shared__ float sms[16 * 16 * 2];
    __shared__ float smh[16];

    const size_t row0 = (size_t)b * N + n0;

    if (tid < 128) {
        const float* lrow = Lp + (row0 + tid) * 128 + b * 16;
        bool mk = mask[row0 + tid] != 0;
#pragma unroll
        for (int h = 0; h < 16; h++)
            sl[tid * 16 + h] = mk ? lrow[h] * (1.0f / WSCALE) : -1e30f;
    }
    __syncthreads();
    {
        const int seg = tid >> 4, h = tid & 15;
        float m = -1e30f;
#pragma unroll
        for (int r = 0; r < 8; r++) m = fmaxf(m, sl[(seg * 8 + r) * 16 + h]);
        float s = 0.f;
#pragma unroll
        for (int r = 0; r < 8; r++) s += __expf(sl[(seg * 8 + r) * 16 + h] - m);
        sms[(seg * 16 + h) * 2] = m;
        sms[(seg * 16 + h) * 2 + 1] = s;
    }
    __syncthreads();
    if (tid < 16) {
        float m = -1e30f;
#pragma unroll
        for (int g = 0; g < 16; g++) m = fmaxf(m, sms[(g * 16 + tid) * 2]);
        float s = 0.f;
#pragma unroll
        for (int g = 0; g < 16; g++)
            s += sms[(g * 16 + tid) * 2 + 1] * __expf(sms[(g * 16 + tid) * 2] - m);
        smh[tid] = m;
        if (dh == 0) {
            poolms[(bp * 16 + tid) * 2] = m;
            poolms[(bp * 16 + tid) * 2 + 1] = s;
        }
    }
    __syncthreads();
    for (int i = tid; i < 128 * 16; i += 256)
        sl[i] = __expf(sl[i] - smh[i & 15]);
    __syncthreads();

    const __half2* xp = (const __half2*)(xh + row0 * 1024) + dh * 256 + tid;
    float accx[16], accy[16];
#pragma unroll
    for (int h = 0; h < 16; h++) { accx[h] = 0.f; accy[h] = 0.f; }
    for (int n = 0; n < 128; n++) {
        float2 f = __half22float2(xp[(size_t)n * 512]);
        const float* pn = &sl[n * 16];
#pragma unroll
        for (int h = 0; h < 16; h++) {
            float p = pn[h];
            accx[h] = fmaf(p, f.x, accx[h]);
            accy[h] = fmaf(p, f.y, accy[h]);
        }
    }
#pragma unroll
    for (int h = 0; h < 16; h++) {
        float2 o = {accx[h], accy[h]};
        *(float2*)(poolv + ((size_t)(bp * 16 + h) << 10) + dh * 512 + tid * 2) = o;
    }
}

// fused: merge flash partials -> gk (smem) -> wrp[bh] = diag(gk)*W_r (fp16)
__global__ void __launch_bounds__(256) combinek_wrp_kernel(
    const float* __restrict__ poolv, const float* __restrict__ poolms,
    const float* __restrict__ W_qkv, const float* __restrict__ gq,
    const float* __restrict__ W_r, __half* __restrict__ wrp)
{
    const int bh = blockIdx.x, b = bh >> 4, h = bh & 15;
    const int tid = threadIdx.x;
    __shared__ float wp[32];
    __shared__ float pooled[1024];
    __shared__ float red[256];
    __shared__ float s_gk[64];
    __shared__ float sM;

    if (tid == 0) {
        float M = -1e30f;
        for (int p = 0; p < 32; p++) M = fmaxf(M, poolms[((b * 32 + p) * 16 + h) * 2]);
        sM = M;
    }
    __syncthreads();
    if (tid < 32) {
        float e = __expf(poolms[((b * 32 + tid) * 16 + h) * 2] - sM);
        float se = poolms[((b * 32 + tid) * 16 + h) * 2 + 1] * e;
        float S = se;
#pragma unroll
        for (int o = 16; o; o >>= 1) S += __shfl_xor_sync(0xffffffffu, S, o);
        wp[tid] = e / S;
    }
    __syncthreads();

    for (int i = tid; i < 1024; i += 256) {
        float s = 0.f;
#pragma unroll
        for (int p = 0; p < 32; p++)
            s = fmaf(poolv[((size_t)((b * 32 + p) * 16 + h) << 10) + i], wp[p], s);
        pooled[i] = s;
    }
    __syncthreads();

    const int d = tid & 63, seg = tid >> 6;
    float a = 0.f;
    const float* wcol = W_qkv + 1024 + h * 64 + d;
    for (int i = seg * 256; i < seg * 256 + 256; i++)
        a = fmaf(pooled[i], wcol[(size_t)i * 3072], a);
    red[tid] = a;
    __syncthreads();
    if (tid < 64) {
        float t = red[tid] + red[tid + 64] + red[tid + 128] + red[tid + 192];
        s_gk[tid] = gq[bh * 64 + tid] * t;
    }
    __syncthreads();

    for (int i = tid; i < 4096; i += 256) {
        int e = i >> 6, dd = i & 63;
        wrp[(size_t)bh * 4096 + i] = __float2half(s_gk[dd] * W_r[dd * 64 + e]);
    }
}

// rgemm: r = v_h @ wrp_bh + q + b_r -> A3 fp16.
__global__ void __launch_bounds__(256) rgemm_kernel(
    const __half* __restrict__ qv, const __half* __restrict__ wrp,
    const float* __restrict__ b_r, __half* __restrict__ A3, int N)
{
    const int h = blockIdx.x;
    const size_t row0 = (size_t)blockIdx.y * 128;
    const int b = (int)(row0 >> 12);
    const int bh = b * 16 + h;
    const int tid = threadIdx.x, wid = tid >> 5, lane = tid & 31;

    __shared__ __half sA[128 * 72];
    __shared__ __half sB[64 * 72];
    __shared__ float sbr[64];

#pragma unroll
    for (int i = 0; i < 4; i++) {
        int idx = tid + i * 256;
        int r = idx >> 3, c = (idx & 7) << 3;
        *(uint4*)(&sA[r * 72 + c]) =
            *(const uint4*)(qv + (row0 + r) * 2048 + 1024 + h * 64 + c);
    }
#pragma unroll
    for (int i = 0; i < 2; i++) {
        int idx = tid + i * 256;
        int r = idx >> 3, c = (idx & 7) << 3;
        *(uint4*)(&sB[r * 72 + c]) =
            *(const uint4*)(wrp + (size_t)bh * 4096 + r * 64 + c);
    }
    if (tid < 64) sbr[tid] = b_r[tid];
    __syncthreads();

    const uint32_t smA = smem_u32(sA), smB = smem_u32(sB);
    const int fr = lane & 15;
    const uint32_t fk = (lane & 16) ? 16u : 0u;

    float acc[8][4];
#pragma unroll
    for (int nt = 0; nt < 8; nt++)
#pragma unroll
        for (int e = 0; e < 4; e++) acc[nt][e] = 0.f;

#pragma unroll
    for (int ks = 0; ks < 4; ks++) {
        const uint32_t kb = (uint32_t)ks * 32u + fk;
        uint32_t a[4], bfr[8][2];
        {
            uint32_t addr = smA + (uint32_t)(wid * 16 + fr) * 144 + kb;
            asm volatile("ldmatrix.sync.aligned.m8n8.x4.shared.b16 {%0,%1,%2,%3}, [%4];"
                         : "=r"(a[0]), "=r"(a[1]), "=r"(a[2]), "=r"(a[3]) : "r"(addr));
        }
#pragma unroll
        for (int nb = 0; nb < 4; nb++) {
            uint32_t addr = smB + (uint32_t)(nb * 16 + fr) * 144 + kb;
            uint32_t r0, r1, r2, r3;
            asm volatile("ldmatrix.sync.aligned.m8n8.x4.shared.b16 {%0,%1,%2,%3}, [%4];"
                         : "=r"(r0), "=r"(r1), "=r"(r2), "=r"(r3) : "r"(addr));
            bfr[nb * 2][0] = r0; bfr[nb * 2][1] = r2;
            bfr[nb * 2 + 1][0] = r1; bfr[nb * 2 + 1][1] = r3;
        }
#pragma unroll
        for (int nt = 0; nt < 8; nt++)
            mma16816h(acc[nt], a, bfr[nt]);
    }

    const int r0o = wid * 16 + (lane >> 2);
#pragma unroll
    for (int nt = 0; nt < 8; nt++) {
        const int col = nt * 8 + ((lane & 3) << 1);
        float brx = sbr[col], bry = sbr[col + 1];
        const size_t rA = row0 + r0o, rB = row0 + r0o + 8;
        float2 qa = __half22float2(*(const __half2*)(qv + rA * 2048 + h * 64 + col));
        float2 qb = __half22float2(*(const __half2*)(qv + rB * 2048 + h * 64 + col));
        *(__half2*)(A3 + rA * 1024 + h * 64 + col) =
            __floats2half2_rn(acc[nt][0] + brx + qa.x, acc[nt][1] + bry + qa.y);
        *(__half2*)(A3 + rB * 1024 + h * 64 + col) =
            __floats2half2_rn(acc[nt][2] + brx + qb.x, acc[nt][3] + bry + qb.y);
    }
}

extern "C" void kernel_launch(void* const* d_in, const int* in_sizes, int n_in,
                              void* d_out, int out_size)
{
    const float*         x     = (const float*)d_in[0];
    const unsigned char* mask  = (const unsigned char*)d_in[1];
    const float*         W_qkv = (const float*)d_in[2];
    const float*         w_q   = (const float*)d_in[3];
    const float*         w_k   = (const float*)d_in[4];
    const float*         W_r   = (const float*)d_in[5];
    const float*         b_r   = (const float*)d_in[6];
    const float*         W_out = (const float*)d_in[7];
    const float*         b_out = (const float*)d_in[8];
    float* out = (float*)d_out;

    const int M = in_sizes[0] / 1024;   // 16384
    const int N = M / 4;                // 4096

    __half *xh, *Bqv, *qv, *wekt, *wrp, *B3, *A3;
    float *part, *gq, *vk, *Lp, *poolv, *poolms;
    cudaGetSymbolAddress((void**)&xh, g_xh);
    cudaGetSymbolAddress((void**)&Bqv, g_Bqv);
    cudaGetSymbolAddress((void**)&qv, g_qv);
    cudaGetSymbolAddress((void**)&part, g_part);
    cudaGetSymbolAddress((void**)&gq, g_gq);
    cudaGetSymbolAddress((void**)&vk, g_vk);
    cudaGetSymbolAddress((void**)&wekt, g_wekt);
    cudaGetSymbolAddress((void**)&Lp, g_Lp);
    cudaGetSymbolAddress((void**)&poolv, g_poolv);
    cudaGetSymbolAddress((void**)&poolms, g_poolms);
    cudaGetSymbolAddress((void**)&wrp, g_wrp);
    cudaGetSymbolAddress((void**)&B3, g_B3);
    cudaGetSymbolAddress((void**)&A3, g_A3);

    const int SMEM = STAGES * STAGE_B * 2;  // 110592
    cudaFuncSetAttribute(gemm_mma<true>,  cudaFuncAttributeMaxDynamicSharedMemorySize, SMEM);
    cudaFuncSetAttribute(gemm_mma<false>, cudaFuncAttributeMaxDynamicSharedMemorySize, SMEM);

    // 1) conversions (main stream, serial — R12 arrangement)
    conv_x_kernel<<<M, 256>>>(x, xh);
    conv_w3_kernel<<<dim3(32, 32, 3), dim3(32, 8)>>>(W_qkv, W_out, Bqv, B3);

    // 2) GEMM1q: q = x @ W_qkv[:, :1024]  (fp16 out into qv cols 0..1023)
    gemm_mma<true><<<dim3(8, 128), 256, SMEM>>>(xh, Bqv, nullptr, qv, 1024, 2048);

    // fork: GEMM1v on side stream (only overlap that ever measured positive)
    cudaEventRecord(g_e0, 0);
    cudaStreamWaitEvent(g_s1, g_e0, 0);
    gemm_mma<true><<<dim3(8, 128), 256, SMEM, g_s1>>>(
        xh, Bqv + 1024ull * 1024, nullptr, qv + 1024, 1024, 2048);
    cudaEventRecord(g_e1, g_s1);

    // 3) q-pass pooling -> gq, vk -> wekt (fused)  [main stream]
    mid_part_q<<<64 * PARTS, 256>>>(qv, mask, w_q, part, N);
    combineq_wek_kernel<<<128, 256>>>(part, w_k, W_qkv, gq, vk, wekt);

    // 4) k-pass: logits via tensor-core GEMM, flash pooling of x
    gemm_mma<false><<<dim3(1, 128), 256, SMEM>>>(xh, wekt, nullptr, Lp, 1024, 128);
    poolx2_kernel<<<256, 256>>>(xh, Lp, mask, poolv, poolms, N);
    combinek_wrp_kernel<<<64, 256>>>(poolv, poolms, W_qkv, gq, W_r, wrp);

    // join: v columns ready before rgemm
    cudaStreamWaitEvent(0, g_e1, 0);

    // 5) r = v @ (diag(gk)W_r) + q + b_r  -> fp16
    rgemm_kernel<<<dim3(16, M / 128), 256>>>(qv, wrp, b_r, A3, N);

    // 6) out = r @ W_out + b_out  (fp32 out, K=1024)
    gemm_mma<false><<<dim3(8, 128), 256, SMEM>>>(A3, B3, b_out, out, 1024, 1024);
}

// round 17
// speedup vs baseline: 1.1305x; 1.0109x over previous
#include <cuda_runtime.h>
#include <cuda_fp16.h>
#include <cfloat>
#include <cstdint>

#define HEADS 16
#define DH 64
#define SCALE 0.125f
#define PARTS 8
#define PSTRIDE 68
#define WSCALE 16384.0f

// scratch (__device__ globals; no cudaMalloc allowed)
__device__ __align__(16) __half g_xh[16384ull * 1024];
__device__ __align__(16) __half g_Bqv[2048ull * 1024];
__device__ __align__(16) __half g_qv[16384ull * 2048];
__device__ __align__(16) float  g_part[64 * PARTS * PSTRIDE];
__device__ __align__(16) float  g_gq[64 * 64];
__device__ __align__(16) float  g_vk[64 * 64];
__device__ __align__(16) __half g_wekt[128ull * 1024];
__device__ __align__(16) float  g_Lp[16384ull * 128];
__device__ __align__(16) float  g_poolv[128ull * 16 * 1024];
__device__ __align__(16) float  g_poolms[4096];
__device__ __align__(16) __half g_wrp[64ull * 4096];
__device__ __align__(16) __half g_B3[1024ull * 1024];
__device__ __align__(16) __half g_A3[16384ull * 1024];

// side stream + events, created at load time
static cudaStream_t g_s1;
static cudaEvent_t g_e0, g_e1;
static struct StreamInit {
    StreamInit() {
        cudaStreamCreateWithFlags(&g_s1, cudaStreamNonBlocking);
        cudaEventCreateWithFlags(&g_e0, cudaEventDisableTiming);
        cudaEventCreateWithFlags(&g_e1, cudaEventDisableTiming);
    }
} g_stream_init;

__device__ __forceinline__ uint32_t smem_u32(const void* p) {
    uint32_t a;
    asm("{ .reg .u64 t; cvta.to.shared.u64 t, %1; cvt.u32.u64 %0, t; }" : "=r"(a) : "l"(p));
    return a;
}
__device__ __forceinline__ void cp16(uint32_t dst, const void* src) {
    asm volatile("cp.async.cg.shared.global [%0], [%1], 16;\n" :: "r"(dst), "l"(src));
}
__device__ __forceinline__ void mma16816h(float* c, const uint32_t* a, const uint32_t* b) {
    asm volatile(
        "mma.sync.aligned.m16n8k16.row.col.f32.f16.f16.f32 "
        "{%0,%1,%2,%3}, {%4,%5,%6,%7}, {%8,%9}, {%0,%1,%2,%3};"
        : "+f"(c[0]), "+f"(c[1]), "+f"(c[2]), "+f"(c[3])
        : "r"(a[0]), "r"(a[1]), "r"(a[2]), "r"(a[3]), "r"(b[0]), "r"(b[1]));
}

// ---------------------------------------------------------------------------
// mma.sync fp16 GEMM (byte-identical to R10-R16)
// ---------------------------------------------------------------------------
#define BK_BYTES 128
#define ROWB 144
#define STAGE_B (128 * ROWB)
#define STAGES 3

template <bool HALF_OUT>
__global__ void __launch_bounds__(256, 2) gemm_mma(
    const void* __restrict__ Av, const void* __restrict__ Bv,
    const float* __restrict__ bias, void* __restrict__ Cv, int Kp, int Ntot)
{
    extern __shared__ char dsm[];
    const uint32_t aoff = smem_u32(dsm);
    const uint32_t boff = aoff + STAGES * STAGE_B;

    const int tid = threadIdx.x, wid = tid >> 5, lane = tid & 31;
    const int m0 = blockIdx.y << 7, n0 = blockIdx.x << 7;
    const int warp_m = (wid & 1) << 6;
    const int warp_n = (wid >> 1) << 5;

    const size_t KpB = (size_t)Kp * 2;
    const int nch = Kp >> 6;

    const int lr = tid >> 3;
    const int lc = (tid & 7) << 4;
    const char* Ag = (const char*)Av + (size_t)(m0 + lr) * KpB + lc;
    const char* Bg = (const char*)Bv + (size_t)(n0 + lr) * KpB + lc;
    const uint32_t Asw = aoff + (uint32_t)lr * ROWB + lc;
    const uint32_t Bsw = boff + (uint32_t)lr * ROWB + lc;

#define ISSUE(c, s) do {                                                      \
    size_t kb_ = (size_t)(c) * BK_BYTES;                                      \
    uint32_t so_ = (uint32_t)(s) * STAGE_B;                                   \
    _Pragma("unroll")                                                         \
    for (int i_ = 0; i_ < 4; i_++) {                                          \
        cp16(Asw + so_ + i_ * 32 * ROWB, Ag + kb_ + (size_t)i_ * 32 * KpB);   \
        cp16(Bsw + so_ + i_ * 32 * ROWB, Bg + kb_ + (size_t)i_ * 32 * KpB);   \
    }                                                                         \
    asm volatile("cp.async.commit_group;");                                   \
} while (0)

    float acc[4][4][4];
#pragma unroll
    for (int i = 0; i < 4; i++)
#pragma unroll
        for (int j = 0; j < 4; j++)
#pragma unroll
            for (int e = 0; e < 4; e++) acc[i][j][e] = 0.f;

    ISSUE(0, 0);
    ISSUE(1, 1);

    const int fr = lane & 15;
    const uint32_t fk = (lane & 16) ? 16u : 0u;

    for (int c = 0; c < nch; c++) {
        const int s = c % STAGES;
        if (c + 2 < nch) { asm volatile("cp.async.wait_group 1;"); }
        else             { asm volatile("cp.async.wait_group 0;"); }
        __syncthreads();
        if (c + 2 < nch) ISSUE(c + 2, (c + 2) % STAGES);

        const uint32_t as_ = aoff + (uint32_t)s * STAGE_B;
        const uint32_t bs_ = boff + (uint32_t)s * STAGE_B;

#pragma unroll
        for (int ks = 0; ks < 4; ks++) {
            const uint32_t kb = (uint32_t)ks * 32u + fk;
            uint32_t a[4][4], b[4][2];
#pragma unroll
            for (int mt = 0; mt < 4; mt++) {
                uint32_t addr = as_ + (uint32_t)(warp_m + mt * 16 + fr) * ROWB + kb;
                asm volatile("ldmatrix.sync.aligned.m8n8.x4.shared.b16 {%0,%1,%2,%3}, [%4];"
                             : "=r"(a[mt][0]), "=r"(a[mt][1]), "=r"(a[mt][2]), "=r"(a[mt][3])
                             : "r"(addr));
            }
#pragma unroll
            for (int nb = 0; nb < 2; nb++) {
                uint32_t addr = bs_ + (uint32_t)(warp_n + nb * 16 + fr) * ROWB + kb;
                uint32_t r0, r1, r2, r3;
                asm volatile("ldmatrix.sync.aligned.m8n8.x4.shared.b16 {%0,%1,%2,%3}, [%4];"
                             : "=r"(r0), "=r"(r1), "=r"(r2), "=r"(r3) : "r"(addr));
                b[nb * 2][0] = r0; b[nb * 2][1] = r2;
                b[nb * 2 + 1][0] = r1; b[nb * 2 + 1][1] = r3;
            }
#pragma unroll
            for (int mt = 0; mt < 4; mt++)
#pragma unroll
                for (int nt = 0; nt < 4; nt++)
                    mma16816h(acc[mt][nt], a[mt], b[nt]);
        }
    }

#pragma unroll
    for (int nt = 0; nt < 4; nt++) {
        const int n = n0 + warp_n + nt * 8 + ((lane & 3) << 1);
        float bx = 0.f, by = 0.f;
        if (!HALF_OUT && bias) { float2 bb = *(const float2*)(bias + n); bx = bb.x; by = bb.y; }
#pragma unroll
        for (int mt = 0; mt < 4; mt++) {
            const int m = m0 + warp_m + mt * 16 + (lane >> 2);
            if (HALF_OUT) {
                __half* Ch = (__half*)Cv;
                *(__half2*)(Ch + (size_t)m * Ntot + n) =
                    __floats2half2_rn(acc[mt][nt][0], acc[mt][nt][1]);
                *(__half2*)(Ch + (size_t)(m + 8) * Ntot + n) =
                    __floats2half2_rn(acc[mt][nt][2], acc[mt][nt][3]);
            } else {
                float* Cf = (float*)Cv;
                float2 v0 = {acc[mt][nt][0] + bx, acc[mt][nt][1] + by};
                float2 v1 = {acc[mt][nt][2] + bx, acc[mt][nt][3] + by};
                *(float2*)(Cf + (size_t)m * Ntot + n) = v0;
                *(float2*)(Cf + (size_t)(m + 8) * Ntot + n) = v1;
            }
        }
    }
#undef ISSUE
}

// merged prologue: blocks [0, Mx) do x->fp16; blocks [Mx, Mx+3072) do the
// 3 weight transpose jobs (1024 blocks each).
__global__ void __launch_bounds__(256) conv_all_kernel(
    const float* __restrict__ x, const float* __restrict__ W_qkv,
    const float* __restrict__ W_out,
    __half* __restrict__ xh, __half* __restrict__ Bqv, __half* __restrict__ B3,
    int Mx)
{
    const int bx = blockIdx.x;
    const int tid = threadIdx.x;
    if (bx < Mx) {
        size_t g = ((size_t)bx * 256 + tid) * 4;
        float4 v = *(const float4*)(x + g);
        __half2* q = (__half2*)(xh + g);
        q[0] = __floats2half2_rn(v.x, v.y);
        q[1] = __floats2half2_rn(v.z, v.w);
        return;
    }
    __shared__ float t[32][33];
    const int j = bx - Mx;            // 0..3071
    const int z = j >> 10;            // job
    const int jj = j & 1023;          // tile index: 32 x-tiles x 32 y-tiles
    const int n0 = (jj & 31) * 32, k0 = (jj >> 5) * 32;
    const float* W = (z == 2) ? W_out : W_qkv;
    const int srcN = (z == 2) ? 1024 : 3072;
    const int coff = (z == 1) ? 2048 : 0;
    __half* out = (z == 0) ? Bqv : (z == 1) ? (Bqv + 1024ull * 1024) : B3;

    const int tx = tid & 31, ty = tid >> 5;
    for (int i = ty; i < 32; i += 8) t[i][tx] = W[(size_t)(k0 + i) * srcN + coff + n0 + tx];
    __syncthreads();
    for (int i = ty; i < 32; i += 8)
        out[(size_t)(n0 + i) * 1024 + k0 + tx] = __float2half(t[tx][i]);
}

// q-pass partial softmax-pooling, SINGLE PASS (online flash update).
__global__ void __launch_bounds__(256) mid_part_q(
    const __half* __restrict__ qv, const unsigned char* __restrict__ mask,
    const float* __restrict__ w_q, float* __restrict__ partials, int N)
{
    const int bh = blockIdx.x / PARTS, part = blockIdx.x % PARTS;
    const int b = bh >> 4, h = bh & 15;
    const int tid = threadIdx.x, lane = tid & 31, wid = tid >> 5;
    const int rows = N / PARTS;
    const int nbase = part * rows;

    __shared__ float s_vec[64];
    __shared__ float s_red[8];
    __shared__ float s_acc[8][64];
    __shared__ float s_m;

    const __half* base = qv + ((size_t)b * N + nbase) * 2048 + h * DH;
    const unsigned char* mrow = mask + (size_t)b * N + nbase;

    if (tid < 64) s_vec[tid] = w_q[tid] * SCALE;
    __syncthreads();

    float m_t = -1e30f, s_t = 0.f;
    float acc[DH];
#pragma unroll
    for (int d = 0; d < DH; d++) acc[d] = 0.f;

    for (int i = tid; i < rows; i += 256) {
        uint4 rv[8];
        const uint4* r4 = (const uint4*)(base + (size_t)i * 2048);
#pragma unroll
        for (int u = 0; u < 8; u++) rv[u] = r4[u];

        float dot = 0.f;
#pragma unroll
        for (int u = 0; u < 8; u++) {
            const __half2* hp = (const __half2*)&rv[u];
#pragma unroll
            for (int j = 0; j < 4; j++) {
                float2 f = __half22float2(hp[j]);
                dot += f.x * s_vec[u * 8 + 2 * j] + f.y * s_vec[u * 8 + 2 * j + 1];
            }
        }
        const bool mk = mrow[i] != 0;
        const float lg = mk ? dot : -1e30f;
        const float nm = fmaxf(m_t, lg);
        const float scale = __expf(m_t - nm);       // 0 on first live row
        const float p = mk ? __expf(lg - nm) : 0.f;
        s_t = s_t * scale + p;
#pragma unroll
        for (int u = 0; u < 8; u++) {
            const __half2* hp = (const __half2*)&rv[u];
#pragma unroll
            for (int j = 0; j < 4; j++) {
                float2 f = __half22float2(hp[j]);
                const int d = u * 8 + 2 * j;
                acc[d]     = acc[d] * scale + p * f.x;
                acc[d + 1] = acc[d + 1] * scale + p * f.y;
            }
        }
        m_t = nm;
    }

    // block max
    float wm = m_t;
#pragma unroll
    for (int o = 16; o; o >>= 1) wm = fmaxf(wm, __shfl_xor_sync(~0u, wm, o));
    if (lane == 0) s_red[wid] = wm;
    __syncthreads();
    if (tid == 0) {
        float m = s_red[0];
        for (int i = 1; i < 8; i++) m = fmaxf(m, s_red[i]);
        s_m = m;
    }
    __syncthreads();
    const float M = s_m;

    // rescale local partials to block max, then tree-sum
    const float sc = __expf(m_t - M);
    float lsum = s_t * sc;
#pragma unroll
    for (int d = 0; d < DH; d++) acc[d] *= sc;

#pragma unroll
    for (int o = 16; o; o >>= 1) lsum += __shfl_xor_sync(~0u, lsum, o);
#pragma unroll
    for (int d = 0; d < DH; d++) {
        float v = acc[d];
#pragma unroll
        for (int o = 16; o; o >>= 1) v += __shfl_xor_sync(~0u, v, o);
        if (lane == 0) s_acc[wid][d] = v;
    }
    __syncthreads();
    if (lane == 0) s_red[wid] = lsum;
    __syncthreads();

    float* po = partials + (size_t)(bh * PARTS + part) * PSTRIDE;
    if (tid == 0) {
        float s = 0.f;
        for (int i = 0; i < 8; i++) s += s_red[i];
        po[0] = M;
        po[1] = s;
    }
    if (tid < 64) {
        float v = 0.f;
#pragma unroll
        for (int w = 0; w < 8; w++) v += s_acc[w][tid];
        po[2 + tid] = v;
    }
}

// fused: merge q-pass partials -> gq, vk; then wekt rows for this bh.
__global__ void __launch_bounds__(256) combineq_wek_kernel(
    const float* __restrict__ partials, const float* __restrict__ w_k,
    const float* __restrict__ W_qkv,
    float* __restrict__ gq, float* __restrict__ vk, __half* __restrict__ wekt)
{
    const int bh = blockIdx.x, tid = threadIdx.x;
    if (bh >= 64) {
        for (int i = tid; i < 1024; i += 256)
            wekt[(size_t)bh * 1024 + i] = __float2half(0.f);
        return;
    }
    __shared__ float s_vk[64];
    if (tid < 64) {
        const int d = tid;
        const float* p = partials + (size_t)bh * PARTS * PSTRIDE;
        float m = -FLT_MAX;
#pragma unroll
        for (int i = 0; i < PARTS; i++) m = fmaxf(m, p[i * PSTRIDE]);
        float s = 0.f, v = 0.f;
#pragma unroll
        for (int i = 0; i < PARTS; i++) {
            float e = __expf(p[i * PSTRIDE] - m);
            s += p[i * PSTRIDE + 1] * e;
            v += p[i * PSTRIDE + 2 + d] * e;
        }
        float pooled = v / s;
        gq[bh * 64 + d] = pooled;
        float vkd = pooled * w_k[d] * SCALE;
        vk[bh * 64 + d] = vkd;
        s_vk[d] = vkd;
    }
    __syncthreads();
    const int h = bh & 15;
    for (int i = tid; i < 1024; i += 256) {
        const float* wrow = W_qkv + (size_t)i * 3072 + 1024 + h * 64;
        float s = 0.f;
#pragma unroll
        for (int d = 0; d < 64; d++) s = fmaf(wrow[d], s_vk[d], s);
        wekt[(size_t)bh * 1024 + i] = __float2half(s * WSCALE);
    }
}

// flash partial pooling of x with k-softmax weights (32 parts x 128 rows)
__global__ void __launch_bounds__(256) poolx2_kernel(
    const __half* __restrict__ xh, const float* __restrict__ Lp,
    const unsigned char* __restrict__ mask,
    float* __restrict__ poolv, float* __restrict__ poolms, int N)
{
    const int blk = blockIdx.x;
    const int dh = blk & 1;
    const int bp = blk >> 1;
    const int b = bp >> 5, part = bp & 31;
    const int rows = N / 32;
    const int n0 = part * rows;
    const int tid = threadIdx.x;

    __shared__ float sl[128 * 16];
    __shared__ float sms[16 * 16 * 2];
    __shared__ float smh[16];

    const size_t row0 = (size_t)b * N + n0;

    if (tid < 128) {
        const float* lrow = Lp + (row0 + tid) * 128 + b * 16;
        bool mk = mask[row0 + tid] != 0;
#pragma unroll
        for (int h = 0; h < 16; h++)
            sl[tid * 16 + h] = mk ? lrow[h] * (1.0f / WSCALE) : -1e30f;
    }
    __syncthreads();
    {
        const int seg = tid >> 4, h = tid & 15;
        float m = -1e30f;
#pragma unroll
        for (int r = 0; r < 8; r++) m = fmaxf(m, sl[(seg * 8 + r) * 16 + h]);
        float s = 0.f;
#pragma unroll
        for (int r = 0; r < 8; r++) s += __expf(sl[(seg * 8 + r) * 16 + h] - m);
        sms[(seg * 16 + h) * 2] = m;
        sms[(seg * 16 + h) * 2 + 1] = s;
    }
    __syncthreads();
    if (tid < 16) {
        float m = -1e30f;
#pragma unroll
        for (int g = 0; g < 16; g++) m = fmaxf(m, sms[(g * 16 + tid) * 2]);
        float s = 0.f;
#pragma unroll
        for (int g = 0; g < 16; g++)
            s += sms[(g * 16 + tid) * 2 + 1] * __expf(sms[(g * 16 + tid) * 2] - m);
        smh[tid] = m;
        if (dh == 0) {
            poolms[(bp * 16 + tid) * 2] = m;
            poolms[(bp * 16 + tid) * 2 + 1] = s;
        }
    }
    __syncthreads();
    for (int i = tid; i < 128 * 16; i += 256)
        sl[i] = __expf(sl[i] - smh[i & 15]);
    __syncthreads();

    const __half2* xp = (const __half2*)(xh + row0 * 1024) + dh * 256 + tid;
    float accx[16], accy[16];
#pragma unroll
    for (int h = 0; h < 16; h++) { accx[h] = 0.f; accy[h] = 0.f; }
    for (int n = 0; n < 128; n++) {
        float2 f = __half22float2(xp[(size_t)n * 512]);
        const float* pn = &sl[n * 16];
#pragma unroll
        for (int h = 0; h < 16; h++) {
            float p = pn[h];
            accx[h] = fmaf(p, f.x, accx[h]);
            accy[h] = fmaf(p, f.y, accy[h]);
        }
    }
#pragma unroll
    for (int h = 0; h < 16; h++) {
        float2 o = {accx[h], accy[h]};
        *(float2*)(poolv + ((size_t)(bp * 16 + h) << 10) + dh * 512 + tid * 2) = o;
    }
}

// fused: merge flash partials -> gk (smem) -> wrp[bh] = diag(gk)*W_r (fp16)
__global__ void __launch_bounds__(256) combinek_wrp_kernel(
    const float* __restrict__ poolv, const float* __restrict__ poolms,
    const float* __restrict__ W_qkv, const float* __restrict__ gq,
    const float* __restrict__ W_r, __half* __restrict__ wrp)
{
    const int bh = blockIdx.x, b = bh >> 4, h = bh & 15;
    const int tid = threadIdx.x;
    __shared__ float wp[32];
    __shared__ float pooled[1024];
    __shared__ float red[256];
    __shared__ float s_gk[64];
    __shared__ float sM;

    if (tid == 0) {
        float M = -1e30f;
        for (int p = 0; p < 32; p++) M = fmaxf(M, poolms[((b * 32 + p) * 16 + h) * 2]);
        sM = M;
    }
    __syncthreads();
    if (tid < 32) {
        float e = __expf(poolms[((b * 32 + tid) * 16 + h) * 2] - sM);
        float se = poolms[((b * 32 + tid) * 16 + h) * 2 + 1] * e;
        float S = se;
#pragma unroll
        for (int o = 16; o; o >>= 1) S += __shfl_xor_sync(0xffffffffu, S, o);
        wp[tid] = e / S;
    }
    __syncthreads();

    for (int i = tid; i < 1024; i += 256) {
        float s = 0.f;
#pragma unroll
        for (int p = 0; p < 32; p++)
            s = fmaf(poolv[((size_t)((b * 32 + p) * 16 + h) << 10) + i], wp[p], s);
        pooled[i] = s;
    }
    __syncthreads();

    const int d = tid & 63, seg = tid >> 6;
    float a = 0.f;
    const float* wcol = W_qkv + 1024 + h * 64 + d;
    for (int i = seg * 256; i < seg * 256 + 256; i++)
        a = fmaf(pooled[i], wcol[(size_t)i * 3072], a);
    red[tid] = a;
    __syncthreads();
    if (tid < 64) {
        float t = red[tid] + red[tid + 64] + red[tid + 128] + red[tid + 192];
        s_gk[tid] = gq[bh * 64 + tid] * t;
    }
    __syncthreads();

    for (int i = tid; i < 4096; i += 256) {
        int e = i >> 6, dd = i & 63;
        wrp[(size_t)bh * 4096 + i] = __float2half(s_gk[dd] * W_r[dd * 64 + e]);
    }
}

// rgemm: r = v_h @ wrp_bh + q + b_r -> A3 fp16.
__global__ void __launch_bounds__(256) rgemm_kernel(
    const __half* __restrict__ qv, const __half* __restrict__ wrp,
    const float* __restrict__ b_r, __half* __restrict__ A3, int N)
{
    const int h = blockIdx.x;
    const size_t row0 = (size_t)blockIdx.y * 128;
    const int b = (int)(row0 >> 12);
    const int bh = b * 16 + h;
    const int tid = threadIdx.x, wid = tid >> 5, lane = tid & 31;

    __shared__ __half sA[128 * 72];
    __shared__ __half sB[64 * 72];
    __shared__ float sbr[64];

#pragma unroll
    for (int i = 0; i < 4; i++) {
        int idx = tid + i * 256;
        int r = idx >> 3, c = (idx & 7) << 3;
        *(uint4*)(&sA[r * 72 + c]) =
            *(const uint4*)(qv + (row0 + r) * 2048 + 1024 + h * 64 + c);
    }
#pragma unroll
    for (int i = 0; i < 2; i++) {
        int idx = tid + i * 256;
        int r = idx >> 3, c = (idx & 7) << 3;
        *(uint4*)(&sB[r * 72 + c]) =
            *(const uint4*)(wrp + (size_t)bh * 4096 + r * 64 + c);
    }
    if (tid < 64) sbr[tid] = b_r[tid];
    __syncthreads();

    const uint32_t smA = smem_u32(sA), smB = smem_u32(sB);
    const int fr = lane & 15;
    const uint32_t fk = (lane & 16) ? 16u : 0u;

    float acc[8][4];
#pragma unroll
    for (int nt = 0; nt < 8; nt++)
#pragma unroll
        for (int e = 0; e < 4; e++) acc[nt][e] = 0.f;

#pragma unroll
    for (int ks = 0; ks < 4; ks++) {
        const uint32_t kb = (uint32_t)ks * 32u + fk;
        uint32_t a[4], bfr[8][2];
        {
            uint32_t addr = smA + (uint32_t)(wid * 16 + fr) * 144 + kb;
            asm volatile("ldmatrix.sync.aligned.m8n8.x4.shared.b16 {%0,%1,%2,%3}, [%4];"
                         : "=r"(a[0]), "=r"(a[1]), "=r"(a[2]), "=r"(a[3]) : "r"(addr));
        }
#pragma unroll
        for (int nb = 0; nb < 4; nb++) {
            uint32_t addr = smB + (uint32_t)(nb * 16 + fr) * 144 + kb;
            uint32_t r0, r1, r2, r3;
            asm volatile("ldmatrix.sync.aligned.m8n8.x4.shared.b16 {%0,%1,%2,%3}, [%4];"
                         : "=r"(r0), "=r"(r1), "=r"(r2), "=r"(r3) : "r"(addr));
            bfr[nb * 2][0] = r0; bfr[nb * 2][1] = r2;
            bfr[nb * 2 + 1][0] = r1; bfr[nb * 2 + 1][1] = r3;
        }
#pragma unroll
        for (int nt = 0; nt < 8; nt++)
            mma16816h(acc[nt], a, bfr[nt]);
    }

    const int r0o = wid * 16 + (lane >> 2);
#pragma unroll
    for (int nt = 0; nt < 8; nt++) {
        const int col = nt * 8 + ((lane & 3) << 1);
        float brx = sbr[col], bry = sbr[col + 1];
        const size_t rA = row0 + r0o, rB = row0 + r0o + 8;
        float2 qa = __half22float2(*(const __half2*)(qv + rA * 2048 + h * 64 + col));
        float2 qb = __half22float2(*(const __half2*)(qv + rB * 2048 + h * 64 + col));
        *(__half2*)(A3 + rA * 1024 + h * 64 + col) =
            __floats2half2_rn(acc[nt][0] + brx + qa.x, acc[nt][1] + bry + qa.y);
        *(__half2*)(A3 + rB * 1024 + h * 64 + col) =
            __floats2half2_rn(acc[nt][2] + brx + qb.x, acc[nt][3] + bry + qb.y);
    }
}

extern "C" void kernel_launch(void* const* d_in, const int* in_sizes, int n_in,
                              void* d_out, int out_size)
{
    const float*         x     = (const float*)d_in[0];
    const unsigned char* mask  = (const unsigned char*)d_in[1];
    const float*         W_qkv = (const float*)d_in[2];
    const float*         w_q   = (const float*)d_in[3];
    const float*         w_k   = (const float*)d_in[4];
    const float*         W_r   = (const float*)d_in[5];
    const float*         b_r   = (const float*)d_in[6];
    const float*         W_out = (const float*)d_in[7];
    const float*         b_out = (const float*)d_in[8];
    float* out = (float*)d_out;

    const int M = in_sizes[0] / 1024;   // 16384
    const int N = M / 4;                // 4096

    __half *xh, *Bqv, *qv, *wekt, *wrp, *B3, *A3;
    float *part, *gq, *vk, *Lp, *poolv, *poolms;
    cudaGetSymbolAddress((void**)&xh, g_xh);
    cudaGetSymbolAddress((void**)&Bqv, g_Bqv);
    cudaGetSymbolAddress((void**)&qv, g_qv);
    cudaGetSymbolAddress((void**)&part, g_part);
    cudaGetSymbolAddress((void**)&gq, g_gq);
    cudaGetSymbolAddress((void**)&vk, g_vk);
    cudaGetSymbolAddress((void**)&wekt, g_wekt);
    cudaGetSymbolAddress((void**)&Lp, g_Lp);
    cudaGetSymbolAddress((void**)&poolv, g_poolv);
    cudaGetSymbolAddress((void**)&poolms, g_poolms);
    cudaGetSymbolAddress((void**)&wrp, g_wrp);
    cudaGetSymbolAddress((void**)&B3, g_B3);
    cudaGetSymbolAddress((void**)&A3, g_A3);

    const int SMEM = STAGES * STAGE_B * 2;  // 110592
    cudaFuncSetAttribute(gemm_mma<true>,  cudaFuncAttributeMaxDynamicSharedMemorySize, SMEM);
    cudaFuncSetAttribute(gemm_mma<false>, cudaFuncAttributeMaxDynamicSharedMemorySize, SMEM);

    // 1) conversions (one merged launch)
    conv_all_kernel<<<M + 3072, 256>>>(x, W_qkv, W_out, xh, Bqv, B3, M);

    // 2) GEMM1q: q = x @ W_qkv[:, :1024]
    gemm_mma<true><<<dim3(8, 128), 256, SMEM>>>(xh, Bqv, nullptr, qv, 1024, 2048);

    // fork: GEMM1v on side stream
    cudaEventRecord(g_e0, 0);
    cudaStreamWaitEvent(g_s1, g_e0, 0);
    gemm_mma<true><<<dim3(8, 128), 256, SMEM, g_s1>>>(
        xh, Bqv + 1024ull * 1024, nullptr, qv + 1024, 1024, 2048);
    cudaEventRecord(g_e1, g_s1);

    // 3) q-pass pooling (single-pass online) -> gq, vk -> wekt
    mid_part_q<<<64 * PARTS, 256>>>(qv, mask, w_q, part, N);
    combineq_wek_kernel<<<128, 256>>>(part, w_k, W_qkv, gq, vk, wekt);

    // 4) k-pass: logits via tensor-core GEMM, flash pooling of x
    gemm_mma<false><<<dim3(1, 128), 256, SMEM>>>(xh, wekt, nullptr, Lp, 1024, 128);
    poolx2_kernel<<<256, 256>>>(xh, Lp, mask, poolv, poolms, N);
    combinek_wrp_kernel<<<64, 256>>>(poolv, poolms, W_qkv, gq, W_r, wrp);

    // join: v columns ready before rgemm
    cudaStreamWaitEvent(0, g_e1, 0);

    // 5) r = v @ (diag(gk)W_r) + q + b_r  -> fp16
    rgemm_kernel<<<dim3(16, M / 128), 256>>>(qv, wrp, b_r, A3, N);

    // 6) out = r @ W_out + b_out
    gemm_mma<false><<<dim3(8, 128), 256, SMEM>>>(A3, B3, b_out, out, 1024, 1024);
}